// round 16
// baseline (speedup 1.0000x reference)
#include <cuda_runtime.h>
#include <cstdint>
#include <math.h>

typedef unsigned long long u64;

// Problem constants
#define Tt 512
#define Bb 256
#define Dd 256
#define Hh 1024
#define Rr 64

// Scan tiling
#define BT 8     // batch rows per cluster (4 f32x2 pairs)
#define HT 128   // hidden slice per CTA
#define NH 8     // cluster size

// Scratch
__device__ float g_xw1[(size_t)Tt * Bb * Rr];          // 33.5 MB
__device__ float g_wx2[(size_t)Tt * Bb * Hh];          // 537 MB

// ---------------- packed f32x2 helpers ----------------
__device__ __forceinline__ u64 fma2(u64 a, u64 b, u64 c) {
    u64 d;
    asm("fma.rn.f32x2 %0, %1, %2, %3;" : "=l"(d) : "l"(a), "l"(b), "l"(c));
    return d;
}
__device__ __forceinline__ u64 add2(u64 a, u64 b) {
    u64 d;
    asm("add.rn.f32x2 %0, %1, %2;" : "=l"(d) : "l"(a), "l"(b));
    return d;
}
__device__ __forceinline__ u64 dup2(float x) {
    u64 d;
    asm("mov.b64 %0, {%1, %1};" : "=l"(d) : "f"(x));
    return d;
}
__device__ __forceinline__ u64 pack2(float x, float y) {
    u64 d;
    asm("mov.b64 %0, {%1, %2};" : "=l"(d) : "f"(x), "f"(y));
    return d;
}
__device__ __forceinline__ void unpack2(u64 v, float& x, float& y) {
    asm("mov.b64 {%0, %1}, %2;" : "=f"(x), "=f"(y) : "l"(v));
}
__device__ __forceinline__ void cluster_sync_() {
    asm volatile("barrier.cluster.arrive.aligned;" ::: "memory");
    asm volatile("barrier.cluster.wait.aligned;" ::: "memory");
}
__device__ __forceinline__ uint32_t mapa_rank(uint32_t laddr, uint32_t rank) {
    uint32_t r;
    asm("mapa.shared::cluster.u32 %0, %1, %2;" : "=r"(r) : "r"(laddr), "r"(rank));
    return r;
}
__device__ __forceinline__ float4 ld_dsmem4(uint32_t addr) {
    float4 v;
    asm volatile("ld.shared::cluster.v4.f32 {%0, %1, %2, %3}, [%4];"
                 : "=f"(v.x), "=f"(v.y), "=f"(v.z), "=f"(v.w) : "r"(addr));
    return v;
}
__device__ __forceinline__ float sigmoidf_(float x) {
    return 1.0f / (1.0f + __expf(-x));
}

// ======================================================================
// Kernel 1: xw1[m][r] = sum_d x[m][d] * W1[r][d]   (M=131072, K=256, N=64)
// 128m x 64r tile, K staged in 4 chunks of 64. f32x2 accum over m-pairs.
// ======================================================================
#define XP 132   // x tile pitch (mult of 4 -> 16B-aligned k rows)
#define WP 68    // W1 tile pitch
#define XW1_SMEM ((64 * XP + 64 * WP) * 4)

__global__ void __launch_bounds__(256) xw1_kernel(const float* __restrict__ x,
                                                  const float* __restrict__ W1)
{
    extern __shared__ float smx[];
    float* Xs = smx;             // [64 k][XP] m-major rows
    float* Ws = smx + 64 * XP;   // [64 k][WP] r-major rows

    const int tid = threadIdx.x;
    const int m0  = blockIdx.x * 128;
    const int tx  = tid & 7;     // r block of 8
    const int ty  = tid >> 3;    // m block of 4 (2 m-pairs)

    u64 acc[2][8];
    #pragma unroll
    for (int i = 0; i < 2; i++)
        #pragma unroll
        for (int j = 0; j < 8; j++) acc[i][j] = 0ull;

    for (int kk = 0; kk < Dd; kk += 64) {
        #pragma unroll
        for (int i = 0; i < 8; i++) {
            int s   = tid + i * 256;       // 0..2047
            int row = s >> 4;              // 0..127
            int kq  = s & 15;
            float4 a = *(const float4*)(x + (size_t)(m0 + row) * Dd + kk + kq * 4);
            Xs[(kq * 4 + 0) * XP + row] = a.x;
            Xs[(kq * 4 + 1) * XP + row] = a.y;
            Xs[(kq * 4 + 2) * XP + row] = a.z;
            Xs[(kq * 4 + 3) * XP + row] = a.w;
        }
        #pragma unroll
        for (int i = 0; i < 4; i++) {
            int s   = tid + i * 256;       // 0..1023
            int row = s >> 4;              // 0..63
            int kq  = s & 15;
            float4 b = *(const float4*)(W1 + (size_t)row * Dd + kk + kq * 4);
            Ws[(kq * 4 + 0) * WP + row] = b.x;
            Ws[(kq * 4 + 1) * WP + row] = b.y;
            Ws[(kq * 4 + 2) * WP + row] = b.z;
            Ws[(kq * 4 + 3) * WP + row] = b.w;
        }
        __syncthreads();

        #pragma unroll 4
        for (int k = 0; k < 64; k++) {
            const u64* ap = (const u64*)(Xs + k * XP + ty * 4);   // 2 m-pairs
            u64 a0 = ap[0], a1 = ap[1];
            const float* bp = Ws + k * WP + tx * 8;
            float4 b0 = *(const float4*)(bp);
            float4 b1 = *(const float4*)(bp + 4);
            float bs[8] = {b0.x, b0.y, b0.z, b0.w, b1.x, b1.y, b1.z, b1.w};
            #pragma unroll
            for (int j = 0; j < 8; j++) {
                u64 bd = dup2(bs[j]);
                acc[0][j] = fma2(a0, bd, acc[0][j]);
                acc[1][j] = fma2(a1, bd, acc[1][j]);
            }
        }
        __syncthreads();
    }

    #pragma unroll
    for (int p = 0; p < 2; p++) {
        float lo[8], hi[8];
        #pragma unroll
        for (int j = 0; j < 8; j++) unpack2(acc[p][j], lo[j], hi[j]);
        size_t r0 = (size_t)(m0 + ty * 4 + 2 * p)     * Rr + tx * 8;
        size_t r1 = (size_t)(m0 + ty * 4 + 2 * p + 1) * Rr + tx * 8;
        *(float4*)(g_xw1 + r0)     = make_float4(lo[0], lo[1], lo[2], lo[3]);
        *(float4*)(g_xw1 + r0 + 4) = make_float4(lo[4], lo[5], lo[6], lo[7]);
        *(float4*)(g_xw1 + r1)     = make_float4(hi[0], hi[1], hi[2], hi[3]);
        *(float4*)(g_xw1 + r1 + 4) = make_float4(hi[4], hi[5], hi[6], hi[7]);
    }
}

// ======================================================================
// Kernel 2: wx2[m][h] = sum_r xw1[m][r] * W2[h][r]  (unchanged)
// ======================================================================
#define PM 132
__global__ void __launch_bounds__(256) wx2_kernel(const float* __restrict__ W2)
{
    extern __shared__ float smg[];
    float* Ast = smg;
    float* Bst = smg + 64 * PM;

    const int tid = threadIdx.x;
    const int m0  = blockIdx.x * 128;
    const int h0  = blockIdx.y * 128;

    #pragma unroll
    for (int i = 0; i < 8; i++) {
        int s  = tid + i * 256;
        int mm = s >> 4;
        int rq = s & 15;
        float4 a = *(const float4*)(g_xw1 + (size_t)(m0 + mm) * 64 + rq * 4);
        Ast[(rq * 4 + 0) * PM + mm] = a.x;
        Ast[(rq * 4 + 1) * PM + mm] = a.y;
        Ast[(rq * 4 + 2) * PM + mm] = a.z;
        Ast[(rq * 4 + 3) * PM + mm] = a.w;
        float4 b = *(const float4*)(W2 + (size_t)(h0 + mm) * 64 + rq * 4);
        Bst[(rq * 4 + 0) * PM + mm] = b.x;
        Bst[(rq * 4 + 1) * PM + mm] = b.y;
        Bst[(rq * 4 + 2) * PM + mm] = b.z;
        Bst[(rq * 4 + 3) * PM + mm] = b.w;
    }
    __syncthreads();

    const int tx = tid & 15;
    const int ty = tid >> 4;

    u64 acc[4][8];
    #pragma unroll
    for (int i = 0; i < 4; i++)
        #pragma unroll
        for (int j = 0; j < 8; j++) acc[i][j] = 0ull;

    #pragma unroll 4
    for (int k = 0; k < 64; k++) {
        const u64* ap = (const u64*)(Ast + k * PM + ty * 8);
        u64 a0 = ap[0], a1 = ap[1], a2 = ap[2], a3 = ap[3];
        const float* bp = Bst + k * PM + tx * 8;
        float4 b0 = *(const float4*)(bp);
        float4 b1 = *(const float4*)(bp + 4);
        float bs[8] = {b0.x, b0.y, b0.z, b0.w, b1.x, b1.y, b1.z, b1.w};
        #pragma unroll
        for (int j = 0; j < 8; j++) {
            u64 bd = dup2(bs[j]);
            acc[0][j] = fma2(a0, bd, acc[0][j]);
            acc[1][j] = fma2(a1, bd, acc[1][j]);
            acc[2][j] = fma2(a2, bd, acc[2][j]);
            acc[3][j] = fma2(a3, bd, acc[3][j]);
        }
    }

    #pragma unroll
    for (int i = 0; i < 4; i++) {
        float lo[8], hi[8];
        #pragma unroll
        for (int j = 0; j < 8; j++) unpack2(acc[i][j], lo[j], hi[j]);
        size_t base0 = (size_t)(m0 + ty * 8 + 2 * i)     * Hh + h0 + tx * 8;
        size_t base1 = (size_t)(m0 + ty * 8 + 2 * i + 1) * Hh + h0 + tx * 8;
        *(float4*)(g_wx2 + base0)     = make_float4(lo[0], lo[1], lo[2], lo[3]);
        *(float4*)(g_wx2 + base0 + 4) = make_float4(lo[4], lo[5], lo[6], lo[7]);
        *(float4*)(g_wx2 + base1)     = make_float4(hi[0], hi[1], hi[2], hi[3]);
        *(float4*)(g_wx2 + base1 + 4) = make_float4(hi[4], hi[5], hi[6], hi[7]);
    }
}

// ======================================================================
// Kernel 3: persistent cluster scan — R15 structure with ONLY the AG
// stage changed: 128 threads x 16B remote loads (v4, 2 slots each),
// rank order rotated by jt (port staggering), local rank read via LDS.
// ======================================================================
#define U1P 132
#define U2P 68

// float offsets in dynamic smem (all 16B-aligned)
#define OFF_U1T   0                       // [64 r][U1P]           8448
#define OFF_U2T   8448                    // [128 j][U2P]          8704
#define OFF_H2    17152                   // [4 bp][128 j] f32x2   1024
#define OFF_PPART 18176                   // [4 hg][4 bp][64 r] x2 2048
#define OFF_PPB   20224                   // [2][4 bp][64 r] f32x2 1024 (DSMEM)
#define OFF_PF2   21248                   // [4 bp][64 r] f32x2     512
#define OFF_RED   21760                   // [2 rh][4 bp][128 j] x2 2048
#define OFF_BG    23808                   // [128]
#define OFF_BU    23936                   // [128]
#define SMEM_FLOATS 24064
#define SMEM_BYTES  (SMEM_FLOATS * 4)

__global__ void __cluster_dims__(NH, 1, 1) __launch_bounds__(256, 2)
scan_kernel(const float* __restrict__ h0g,
            const float* __restrict__ U1,
            const float* __restrict__ U2,
            const float* __restrict__ bg_g,
            const float* __restrict__ bu_g,
            const float* __restrict__ zeta,
            const float* __restrict__ nu,
            float* __restrict__ out)
{
    extern __shared__ float sm[];
    const int tid = threadIdx.x;
    const int jt  = blockIdx.x & (NH - 1);   // cluster rank = H slice
    const int bt  = blockIdx.x >> 3;         // batch tile
    const int hgb = jt * HT;
    const int b0  = bt * BT;

    // ---- one-time loads ----
    for (int idx = tid; idx < 64 * HT; idx += 256) {
        int r = idx >> 7, hh = idx & 127;
        sm[OFF_U1T + r * U1P + hh] = U1[(size_t)r * Hh + hgb + hh];   // [r][hh]
    }
    for (int idx = tid; idx < HT * 64; idx += 256) {
        int j = idx >> 6, r = idx & 63;
        sm[OFF_U2T + j * U2P + r] = U2[(size_t)(hgb + j) * Rr + r];   // [j][r]
    }
    for (int idx = tid; idx < 4 * HT; idx += 256) {
        int bp = idx >> 7, j = idx & 127;
        float a = h0g[(size_t)(b0 + 2 * bp)     * Hh + hgb + j];
        float b = h0g[(size_t)(b0 + 2 * bp + 1) * Hh + hgb + j];
        ((u64*)(sm + OFF_H2))[bp * HT + j] = pack2(a, b);
    }
    if (tid < HT) {
        sm[OFF_BG + tid] = bg_g[hgb + tid];
        sm[OFF_BU + tid] = bu_g[hgb + tid];
    }
    const float zs = sigmoidf_(zeta[0]);
    const float ns = sigmoidf_(nu[0]);
    __syncthreads();

    const uint32_t smem_base = (uint32_t)__cvta_generic_to_shared(sm);

    // DSMEM rank bases, rotated order starting at jt+1 (port staggering)
    uint32_t rkb[NH - 1];
    #pragma unroll
    for (int i = 1; i < NH; i++)
        rkb[i - 1] = mapa_rank(smem_base, (uint32_t)((jt + i) & (NH - 1)));

    // phase A mapping: thread = (rA 0..63, hg 0..3)
    const int rA = tid & 63, hg = tid >> 6;
    const int bp2 = hg;
    // phase B mapping: thread = (jB 0..127, rh 0..1)
    const int jB = tid & 127, rh = tid >> 7;
    const int jE = jB, bh = rh;

    const float bgv = sm[OFF_BG + jE];
    const float buv = sm[OFF_BU + jE];

    const float* u1row = sm + OFF_U1T + rA * U1P + hg * 32;
    const float* u2row = sm + OFF_U2T + jB * U2P + rh * 32;
    u64* h2   = (u64*)(sm + OFF_H2);
    u64* ppart= (u64*)(sm + OFF_PPART);
    u64* ppb  = (u64*)(sm + OFF_PPB);
    u64* pf2  = (u64*)(sm + OFF_PF2);
    u64* red  = (u64*)(sm + OFF_RED);

    const float* wsrc0 = g_wx2 + ((size_t)b0 + bh * 4) * Hh + hgb + jE;

    for (int t = 0; t < Tt; t++) {
        const int cur = t & 1;

        // prefetch wx for this step's epilogue (4 batch rows, column jE)
        const float* ws = wsrc0 + (size_t)t * Bb * Hh;
        float wxr0 = ws[0];
        float wxr1 = ws[Hh];
        float wxr2 = ws[2 * Hh];
        float wxr3 = ws[3 * Hh];

        // ---------- phase A: p[b][rA] += h[b][hh] * U1t[hh][rA], hh in hg slice ----------
        {
            u64 a0 = 0, a1 = 0, a2 = 0, a3 = 0;
            const int hbase = hg * 32;
            #pragma unroll
            for (int q = 0; q < 32; q += 4) {
                float4 u4 = *(const float4*)(u1row + q);
                u64 up0 = dup2(u4.x), up1 = dup2(u4.y);
                u64 up2 = dup2(u4.z), up3 = dup2(u4.w);
                #pragma unroll
                for (int bp = 0; bp < 4; bp++) {
                    const u64* hp = h2 + bp * HT + hbase + q;
                    ulonglong2 ha = *(const ulonglong2*)(hp);
                    ulonglong2 hb = *(const ulonglong2*)(hp + 2);
                    u64& acc = (bp == 0) ? a0 : (bp == 1) ? a1 : (bp == 2) ? a2 : a3;
                    acc = fma2(ha.x, up0, acc);
                    acc = fma2(ha.y, up1, acc);
                    acc = fma2(hb.x, up2, acc);
                    acc = fma2(hb.y, up3, acc);
                }
            }
            ppart[(hg * 4 + 0) * 64 + rA] = a0;
            ppart[(hg * 4 + 1) * 64 + rA] = a1;
            ppart[(hg * 4 + 2) * 64 + rA] = a2;
            ppart[(hg * 4 + 3) * 64 + rA] = a3;
        }
        __syncthreads();

        // ---------- local hg-reduce into DSMEM-exposed buffer ----------
        {
            u64 s = ppart[(0 * 4 + bp2) * 64 + rA];
            s = add2(s, ppart[(1 * 4 + bp2) * 64 + rA]);
            s = add2(s, ppart[(2 * 4 + bp2) * 64 + rA]);
            s = add2(s, ppart[(3 * 4 + bp2) * 64 + rA]);
            ppb[cur * 256 + bp2 * 64 + rA] = s;
        }
        cluster_sync_();

        // ---------- DSMEM all-gather: 128 threads, 16B loads, rotated ranks,
        //            local rank via plain LDS ----------
        if (tid < 128) {
            const int s0 = 2 * tid;                       // slot pair s0, s0+1
            // local rank contribution (plain shared load)
            ulonglong2 lv = *(const ulonglong2*)(ppb + cur * 256 + s0);
            u64 acc0 = lv.x, acc1 = lv.y;
            const uint32_t off = (uint32_t)OFF_PPB * 4u
                               + (uint32_t)(cur * 256 + s0) * 8u;
            #pragma unroll
            for (int i = 0; i < NH - 1; i++) {
                float4 v = ld_dsmem4(rkb[i] + off);
                acc0 = add2(acc0, pack2(v.x, v.y));
                acc1 = add2(acc1, pack2(v.z, v.w));
            }
            pf2[s0]     = acc0;
            pf2[s0 + 1] = acc1;
        }
        __syncthreads();

        // ---------- phase B: uh[b][jB] += p[b][r] * U2t[jB][r], r in rh slice ----------
        {
            u64 a0 = 0, a1 = 0, a2 = 0, a3 = 0;
            const int rbase = rh * 32;
            #pragma unroll
            for (int q = 0; q < 32; q += 4) {
                float4 u4 = *(const float4*)(u2row + q);
                u64 up0 = dup2(u4.x), up1 = dup2(u4.y);
                u64 up2 = dup2(u4.z), up3 = dup2(u4.w);
                #pragma unroll
                for (int bp = 0; bp < 4; bp++) {
                    const u64* pp = pf2 + bp * 64 + rbase + q;
                    ulonglong2 pa = *(const ulonglong2*)(pp);
                    ulonglong2 pb = *(const ulonglong2*)(pp + 2);
                    u64& acc = (bp == 0) ? a0 : (bp == 1) ? a1 : (bp == 2) ? a2 : a3;
                    acc = fma2(pa.x, up0, acc);
                    acc = fma2(pa.y, up1, acc);
                    acc = fma2(pb.x, up2, acc);
                    acc = fma2(pb.y, up3, acc);
                }
            }
            red[(rh * 4 + 0) * HT + jB] = a0;
            red[(rh * 4 + 1) * HT + jB] = a1;
            red[(rh * 4 + 2) * HT + jB] = a2;
            red[(rh * 4 + 3) * HT + jB] = a3;
        }
        __syncthreads();

        // ---------- reduce rh halves + epilogue (thread owns 4 b at column jE) ----------
        {
            float wx[4] = {wxr0, wxr1, wxr2, wxr3};
            #pragma unroll
            for (int pi = 0; pi < 2; pi++) {
                int bp = bh * 2 + pi;
                u64 s = add2(red[(0 * 4 + bp) * HT + jE],
                             red[(1 * 4 + bp) * HT + jE]);
                float uh0, uh1;
                unpack2(s, uh0, uh1);
                float ho0, ho1;
                unpack2(h2[bp * HT + jE], ho0, ho1);

                float pre0 = uh0 + wx[pi * 2 + 0];
                float pre1 = uh1 + wx[pi * 2 + 1];

                float z0 = sigmoidf_(pre0 + bgv);
                float z1 = sigmoidf_(pre1 + bgv);

                float y0 = pre0 + buv, y1 = pre1 + buv;
                float e0 = __expf(-2.0f * fabsf(y0));
                float e1 = __expf(-2.0f * fabsf(y1));
                float c0 = copysignf(__fdividef(1.0f - e0, 1.0f + e0), y0);
                float c1 = copysignf(__fdividef(1.0f - e1, 1.0f + e1), y1);

                float hn0 = fmaf(fmaf(zs, 1.0f - z0, ns), c0, z0 * ho0);
                float hn1 = fmaf(fmaf(zs, 1.0f - z1, ns), c1, z1 * ho1);

                h2[bp * HT + jE] = pack2(hn0, hn1);
                size_t ob = ((size_t)t * Bb + b0 + 2 * bp) * Hh + hgb + jE;
                out[ob]      = hn0;
                out[ob + Hh] = hn1;
            }
        }
        __syncthreads();   // h2 update visible before next phase A
    }
}

// ======================================================================
// Launch
// ======================================================================
extern "C" void kernel_launch(void* const* d_in, const int* in_sizes, int n_in,
                              void* d_out, int out_size)
{
    const float* x    = (const float*)d_in[0];
    const float* h0   = (const float*)d_in[1];
    const float* W1   = (const float*)d_in[2];
    const float* W2   = (const float*)d_in[3];
    const float* U1   = (const float*)d_in[4];
    const float* U2   = (const float*)d_in[5];
    const float* bg   = (const float*)d_in[6];
    const float* bu   = (const float*)d_in[7];
    const float* zeta = (const float*)d_in[8];
    const float* nu   = (const float*)d_in[9];
    float* out = (float*)d_out;

    // 1) xw1 = x @ W1^T
    cudaFuncSetAttribute(xw1_kernel, cudaFuncAttributeMaxDynamicSharedMemorySize,
                         XW1_SMEM);
    xw1_kernel<<<(Tt * Bb) / 128, 256, XW1_SMEM>>>(x, W1);

    // 2) wx2 = xw1 @ W2^T
    const int wx2_smem = 2 * 64 * PM * sizeof(float);
    cudaFuncSetAttribute(wx2_kernel, cudaFuncAttributeMaxDynamicSharedMemorySize,
                         wx2_smem);
    dim3 g2((Tt * Bb) / 128, Hh / 128);
    wx2_kernel<<<g2, 256, wx2_smem>>>(W2);

    // 3) persistent cluster scan: 32 clusters x 8 CTAs = 256 CTAs, occ 2
    cudaFuncSetAttribute(scan_kernel, cudaFuncAttributeMaxDynamicSharedMemorySize,
                         SMEM_BYTES);
    scan_kernel<<<(Bb / BT) * NH, 256, SMEM_BYTES>>>(h0, U1, U2, bg, bu,
                                                     zeta, nu, out);
}

// round 17
// speedup vs baseline: 1.0974x; 1.0974x over previous
#include <cuda_runtime.h>
#include <cstdint>
#include <math.h>

typedef unsigned long long u64;

// Problem constants
#define Tt 512
#define Bb 256
#define Dd 256
#define Hh 1024
#define Rr 64

// Scan tiling
#define BT 8     // batch rows per cluster (4 f32x2 pairs)
#define HT 128   // hidden slice per CTA
#define NH 8     // cluster size

// Scratch
__device__ float g_xw1[(size_t)Tt * Bb * Rr];          // 33.5 MB
__device__ float g_wx2[(size_t)Tt * Bb * Hh];          // 537 MB

// ---------------- packed f32x2 helpers ----------------
__device__ __forceinline__ u64 fma2(u64 a, u64 b, u64 c) {
    u64 d;
    asm("fma.rn.f32x2 %0, %1, %2, %3;" : "=l"(d) : "l"(a), "l"(b), "l"(c));
    return d;
}
__device__ __forceinline__ u64 add2(u64 a, u64 b) {
    u64 d;
    asm("add.rn.f32x2 %0, %1, %2;" : "=l"(d) : "l"(a), "l"(b));
    return d;
}
__device__ __forceinline__ u64 dup2(float x) {
    u64 d;
    asm("mov.b64 %0, {%1, %1};" : "=l"(d) : "f"(x));
    return d;
}
__device__ __forceinline__ u64 pack2(float x, float y) {
    u64 d;
    asm("mov.b64 %0, {%1, %2};" : "=l"(d) : "f"(x), "f"(y));
    return d;
}
__device__ __forceinline__ void unpack2(u64 v, float& x, float& y) {
    asm("mov.b64 {%0, %1}, %2;" : "=f"(x), "=f"(y) : "l"(v));
}
__device__ __forceinline__ void cluster_sync_() {
    asm volatile("barrier.cluster.arrive.aligned;" ::: "memory");
    asm volatile("barrier.cluster.wait.aligned;" ::: "memory");
}
__device__ __forceinline__ uint32_t mapa_rank(uint32_t laddr, uint32_t rank) {
    uint32_t r;
    asm("mapa.shared::cluster.u32 %0, %1, %2;" : "=r"(r) : "r"(laddr), "r"(rank));
    return r;
}
__device__ __forceinline__ float2 ld_dsmem2(uint32_t addr) {
    float2 v;
    asm volatile("ld.shared::cluster.v2.f32 {%0, %1}, [%2];"
                 : "=f"(v.x), "=f"(v.y) : "r"(addr));
    return v;
}
__device__ __forceinline__ float sigmoidf_(float x) {
    return 1.0f / (1.0f + __expf(-x));
}

// ======================================================================
// Kernel 1: xw1[m][r] = sum_d x[m][d] * W1[r][d]   (M=131072, K=256, N=64)
// ======================================================================
#define XP 132
#define WP 68
#define XW1_SMEM ((64 * XP + 64 * WP) * 4)

__global__ void __launch_bounds__(256) xw1_kernel(const float* __restrict__ x,
                                                  const float* __restrict__ W1)
{
    extern __shared__ float smx[];
    float* Xs = smx;             // [64 k][XP]
    float* Ws = smx + 64 * XP;   // [64 k][WP]

    const int tid = threadIdx.x;
    const int m0  = blockIdx.x * 128;
    const int tx  = tid & 7;
    const int ty  = tid >> 3;

    u64 acc[2][8];
    #pragma unroll
    for (int i = 0; i < 2; i++)
        #pragma unroll
        for (int j = 0; j < 8; j++) acc[i][j] = 0ull;

    for (int kk = 0; kk < Dd; kk += 64) {
        #pragma unroll
        for (int i = 0; i < 8; i++) {
            int s   = tid + i * 256;
            int row = s >> 4;
            int kq  = s & 15;
            float4 a = *(const float4*)(x + (size_t)(m0 + row) * Dd + kk + kq * 4);
            Xs[(kq * 4 + 0) * XP + row] = a.x;
            Xs[(kq * 4 + 1) * XP + row] = a.y;
            Xs[(kq * 4 + 2) * XP + row] = a.z;
            Xs[(kq * 4 + 3) * XP + row] = a.w;
        }
        #pragma unroll
        for (int i = 0; i < 4; i++) {
            int s   = tid + i * 256;
            int row = s >> 4;
            int kq  = s & 15;
            float4 b = *(const float4*)(W1 + (size_t)row * Dd + kk + kq * 4);
            Ws[(kq * 4 + 0) * WP + row] = b.x;
            Ws[(kq * 4 + 1) * WP + row] = b.y;
            Ws[(kq * 4 + 2) * WP + row] = b.z;
            Ws[(kq * 4 + 3) * WP + row] = b.w;
        }
        __syncthreads();

        #pragma unroll 4
        for (int k = 0; k < 64; k++) {
            const u64* ap = (const u64*)(Xs + k * XP + ty * 4);
            u64 a0 = ap[0], a1 = ap[1];
            const float* bp = Ws + k * WP + tx * 8;
            float4 b0 = *(const float4*)(bp);
            float4 b1 = *(const float4*)(bp + 4);
            float bs[8] = {b0.x, b0.y, b0.z, b0.w, b1.x, b1.y, b1.z, b1.w};
            #pragma unroll
            for (int j = 0; j < 8; j++) {
                u64 bd = dup2(bs[j]);
                acc[0][j] = fma2(a0, bd, acc[0][j]);
                acc[1][j] = fma2(a1, bd, acc[1][j]);
            }
        }
        __syncthreads();
    }

    #pragma unroll
    for (int p = 0; p < 2; p++) {
        float lo[8], hi[8];
        #pragma unroll
        for (int j = 0; j < 8; j++) unpack2(acc[p][j], lo[j], hi[j]);
        size_t r0 = (size_t)(m0 + ty * 4 + 2 * p)     * Rr + tx * 8;
        size_t r1 = (size_t)(m0 + ty * 4 + 2 * p + 1) * Rr + tx * 8;
        *(float4*)(g_xw1 + r0)     = make_float4(lo[0], lo[1], lo[2], lo[3]);
        *(float4*)(g_xw1 + r0 + 4) = make_float4(lo[4], lo[5], lo[6], lo[7]);
        *(float4*)(g_xw1 + r1)     = make_float4(hi[0], hi[1], hi[2], hi[3]);
        *(float4*)(g_xw1 + r1 + 4) = make_float4(hi[4], hi[5], hi[6], hi[7]);
    }
}

// ======================================================================
// Kernel 2: wx2[m][h] = sum_r xw1[m][r] * W2[h][r]  (unchanged)
// ======================================================================
#define PM 132
__global__ void __launch_bounds__(256) wx2_kernel(const float* __restrict__ W2)
{
    extern __shared__ float smg[];
    float* Ast = smg;
    float* Bst = smg + 64 * PM;

    const int tid = threadIdx.x;
    const int m0  = blockIdx.x * 128;
    const int h0  = blockIdx.y * 128;

    #pragma unroll
    for (int i = 0; i < 8; i++) {
        int s  = tid + i * 256;
        int mm = s >> 4;
        int rq = s & 15;
        float4 a = *(const float4*)(g_xw1 + (size_t)(m0 + mm) * 64 + rq * 4);
        Ast[(rq * 4 + 0) * PM + mm] = a.x;
        Ast[(rq * 4 + 1) * PM + mm] = a.y;
        Ast[(rq * 4 + 2) * PM + mm] = a.z;
        Ast[(rq * 4 + 3) * PM + mm] = a.w;
        float4 b = *(const float4*)(W2 + (size_t)(h0 + mm) * 64 + rq * 4);
        Bst[(rq * 4 + 0) * PM + mm] = b.x;
        Bst[(rq * 4 + 1) * PM + mm] = b.y;
        Bst[(rq * 4 + 2) * PM + mm] = b.z;
        Bst[(rq * 4 + 3) * PM + mm] = b.w;
    }
    __syncthreads();

    const int tx = tid & 15;
    const int ty = tid >> 4;

    u64 acc[4][8];
    #pragma unroll
    for (int i = 0; i < 4; i++)
        #pragma unroll
        for (int j = 0; j < 8; j++) acc[i][j] = 0ull;

    #pragma unroll 4
    for (int k = 0; k < 64; k++) {
        const u64* ap = (const u64*)(Ast + k * PM + ty * 8);
        u64 a0 = ap[0], a1 = ap[1], a2 = ap[2], a3 = ap[3];
        const float* bp = Bst + k * PM + tx * 8;
        float4 b0 = *(const float4*)(bp);
        float4 b1 = *(const float4*)(bp + 4);
        float bs[8] = {b0.x, b0.y, b0.z, b0.w, b1.x, b1.y, b1.z, b1.w};
        #pragma unroll
        for (int j = 0; j < 8; j++) {
            u64 bd = dup2(bs[j]);
            acc[0][j] = fma2(a0, bd, acc[0][j]);
            acc[1][j] = fma2(a1, bd, acc[1][j]);
            acc[2][j] = fma2(a2, bd, acc[2][j]);
            acc[3][j] = fma2(a3, bd, acc[3][j]);
        }
    }

    #pragma unroll
    for (int i = 0; i < 4; i++) {
        float lo[8], hi[8];
        #pragma unroll
        for (int j = 0; j < 8; j++) unpack2(acc[i][j], lo[j], hi[j]);
        size_t base0 = (size_t)(m0 + ty * 8 + 2 * i)     * Hh + h0 + tx * 8;
        size_t base1 = (size_t)(m0 + ty * 8 + 2 * i + 1) * Hh + h0 + tx * 8;
        *(float4*)(g_wx2 + base0)     = make_float4(lo[0], lo[1], lo[2], lo[3]);
        *(float4*)(g_wx2 + base0 + 4) = make_float4(lo[4], lo[5], lo[6], lo[7]);
        *(float4*)(g_wx2 + base1)     = make_float4(hi[0], hi[1], hi[2], hi[3]);
        *(float4*)(g_wx2 + base1 + 4) = make_float4(hi[4], hi[5], hi[6], hi[7]);
    }
}

// ======================================================================
// Kernel 3: persistent cluster scan — R15 champion with ONE change:
// phase A remapped so thread = (rAp = tid&31, hg = tid>>5 = warp id)
// computes 2 rows (rA = rAp, rAp+32) over a 16-hh slice: each broadcast
// h-load feeds 2 rows -> h wavefronts halve (512->256 per CTA/step).
// ppart grows to [8 hg][256 slot]; hg-reduce sums 8. AG = exact R15.
// ======================================================================
#define U1P 132
#define U2P 68

// float offsets in dynamic smem (all 16B-aligned)
#define OFF_U1T   0                       // [64 r][U1P]           8448
#define OFF_U2T   8448                    // [128 j][U2P]          8704
#define OFF_H2    17152                   // [4 bp][128 j] f32x2   1024
#define OFF_PPART 18176                   // [8 hg][256 slot] u64  4096
#define OFF_PPB   22272                   // [2][256 slot] u64     1024 (DSMEM)
#define OFF_PF2   23296                   // [256 slot] u64         512
#define OFF_RED   23808                   // [2 rh][4 bp][128 j]   2048
#define OFF_BG    25856                   // [128]
#define OFF_BU    25984                   // [128]
#define SMEM_FLOATS 26112
#define SMEM_BYTES  (SMEM_FLOATS * 4)

__global__ void __cluster_dims__(NH, 1, 1) __launch_bounds__(256, 2)
scan_kernel(const float* __restrict__ h0g,
            const float* __restrict__ U1,
            const float* __restrict__ U2,
            const float* __restrict__ bg_g,
            const float* __restrict__ bu_g,
            const float* __restrict__ zeta,
            const float* __restrict__ nu,
            float* __restrict__ out)
{
    extern __shared__ float sm[];
    const int tid = threadIdx.x;
    const int jt  = blockIdx.x & (NH - 1);   // cluster rank = H slice
    const int bt  = blockIdx.x >> 3;         // batch tile
    const int hgb = jt * HT;
    const int b0  = bt * BT;

    // ---- one-time loads ----
    for (int idx = tid; idx < 64 * HT; idx += 256) {
        int r = idx >> 7, hh = idx & 127;
        sm[OFF_U1T + r * U1P + hh] = U1[(size_t)r * Hh + hgb + hh];   // [r][hh]
    }
    for (int idx = tid; idx < HT * 64; idx += 256) {
        int j = idx >> 6, r = idx & 63;
        sm[OFF_U2T + j * U2P + r] = U2[(size_t)(hgb + j) * Rr + r];   // [j][r]
    }
    for (int idx = tid; idx < 4 * HT; idx += 256) {
        int bp = idx >> 7, j = idx & 127;
        float a = h0g[(size_t)(b0 + 2 * bp)     * Hh + hgb + j];
        float b = h0g[(size_t)(b0 + 2 * bp + 1) * Hh + hgb + j];
        ((u64*)(sm + OFF_H2))[bp * HT + j] = pack2(a, b);
    }
    if (tid < HT) {
        sm[OFF_BG + tid] = bg_g[hgb + tid];
        sm[OFF_BU + tid] = bu_g[hgb + tid];
    }
    const float zs = sigmoidf_(zeta[0]);
    const float ns = sigmoidf_(nu[0]);
    __syncthreads();

    const uint32_t smem_base = (uint32_t)__cvta_generic_to_shared(sm);

    // DSMEM rank bases hoisted (exact R15)
    uint32_t rkb[NH];
    #pragma unroll
    for (int rk = 0; rk < NH; rk++) rkb[rk] = mapa_rank(smem_base, rk);

    // phase A mapping: thread = (rAp 0..31, hg 0..7 = warp id)
    // rows rA = rAp and rAp+32, hh slice [hg*16, hg*16+16)
    const int rAp = tid & 31, hgA = tid >> 5;
    const float* u1r0 = sm + OFF_U1T + rAp * U1P + hgA * 16;
    const float* u1r1 = u1r0 + 32 * U1P;
    // phase B mapping: thread = (jB 0..127, rh 0..1)
    const int jB = tid & 127, rh = tid >> 7;
    const int jE = jB, bh = rh;

    const float bgv = sm[OFF_BG + jE];
    const float buv = sm[OFF_BU + jE];

    const float* u2row = sm + OFF_U2T + jB * U2P + rh * 32;
    u64* h2   = (u64*)(sm + OFF_H2);
    u64* ppart= (u64*)(sm + OFF_PPART);
    u64* ppb  = (u64*)(sm + OFF_PPB);
    u64* pf2  = (u64*)(sm + OFF_PF2);
    u64* red  = (u64*)(sm + OFF_RED);

    const float* wsrc0 = g_wx2 + ((size_t)b0 + bh * 4) * Hh + hgb + jE;

    for (int t = 0; t < Tt; t++) {
        const int cur = t & 1;

        // prefetch wx for this step's epilogue (4 batch rows, column jE)
        const float* ws = wsrc0 + (size_t)t * Bb * Hh;
        float wxr0 = ws[0];
        float wxr1 = ws[Hh];
        float wxr2 = ws[2 * Hh];
        float wxr3 = ws[3 * Hh];

        // ---------- phase A: 2 rows x 4 bp over 16-hh slice ----------
        {
            u64 a00 = 0, a01 = 0, a02 = 0, a03 = 0;   // row rAp
            u64 a10 = 0, a11 = 0, a12 = 0, a13 = 0;   // row rAp+32
            const int hbase = hgA * 16;
            #pragma unroll
            for (int q = 0; q < 16; q += 4) {
                float4 w0 = *(const float4*)(u1r0 + q);
                float4 w1 = *(const float4*)(u1r1 + q);
                u64 w00 = dup2(w0.x), w01 = dup2(w0.y);
                u64 w02 = dup2(w0.z), w03 = dup2(w0.w);
                u64 w10 = dup2(w1.x), w11 = dup2(w1.y);
                u64 w12 = dup2(w1.z), w13 = dup2(w1.w);
                const u64* hb = h2 + hbase + q;
                {
                    ulonglong2 p0 = *(const ulonglong2*)(hb);
                    ulonglong2 p1 = *(const ulonglong2*)(hb + 2);
                    a00 = fma2(p0.x, w00, a00); a00 = fma2(p0.y, w01, a00);
                    a00 = fma2(p1.x, w02, a00); a00 = fma2(p1.y, w03, a00);
                    a10 = fma2(p0.x, w10, a10); a10 = fma2(p0.y, w11, a10);
                    a10 = fma2(p1.x, w12, a10); a10 = fma2(p1.y, w13, a10);
                }
                {
                    ulonglong2 p0 = *(const ulonglong2*)(hb + HT);
                    ulonglong2 p1 = *(const ulonglong2*)(hb + HT + 2);
                    a01 = fma2(p0.x, w00, a01); a01 = fma2(p0.y, w01, a01);
                    a01 = fma2(p1.x, w02, a01); a01 = fma2(p1.y, w03, a01);
                    a11 = fma2(p0.x, w10, a11); a11 = fma2(p0.y, w11, a11);
                    a11 = fma2(p1.x, w12, a11); a11 = fma2(p1.y, w13, a11);
                }
                {
                    ulonglong2 p0 = *(const ulonglong2*)(hb + 2 * HT);
                    ulonglong2 p1 = *(const ulonglong2*)(hb + 2 * HT + 2);
                    a02 = fma2(p0.x, w00, a02); a02 = fma2(p0.y, w01, a02);
                    a02 = fma2(p1.x, w02, a02); a02 = fma2(p1.y, w03, a02);
                    a12 = fma2(p0.x, w10, a12); a12 = fma2(p0.y, w11, a12);
                    a12 = fma2(p1.x, w12, a12); a12 = fma2(p1.y, w13, a12);
                }
                {
                    ulonglong2 p0 = *(const ulonglong2*)(hb + 3 * HT);
                    ulonglong2 p1 = *(const ulonglong2*)(hb + 3 * HT + 2);
                    a03 = fma2(p0.x, w00, a03); a03 = fma2(p0.y, w01, a03);
                    a03 = fma2(p1.x, w02, a03); a03 = fma2(p1.y, w03, a03);
                    a13 = fma2(p0.x, w10, a13); a13 = fma2(p0.y, w11, a13);
                    a13 = fma2(p1.x, w12, a13); a13 = fma2(p1.y, w13, a13);
                }
            }
            u64* pp = ppart + hgA * 256;
            pp[0 * 64 + rAp]      = a00;
            pp[1 * 64 + rAp]      = a01;
            pp[2 * 64 + rAp]      = a02;
            pp[3 * 64 + rAp]      = a03;
            pp[0 * 64 + rAp + 32] = a10;
            pp[1 * 64 + rAp + 32] = a11;
            pp[2 * 64 + rAp + 32] = a12;
            pp[3 * 64 + rAp + 32] = a13;
        }
        __syncthreads();

        // ---------- hg-reduce (8 slices) into DSMEM-exposed buffer ----------
        {
            u64 s = ppart[tid];
            #pragma unroll
            for (int hgi = 1; hgi < 8; hgi++)
                s = add2(s, ppart[hgi * 256 + tid]);
            ppb[cur * 256 + tid] = s;
        }
        cluster_sync_();

        // ---------- DSMEM all-gather: sum partials over 8 ranks (exact R15) ----------
        {
            const uint32_t off = (uint32_t)OFF_PPB * 4u
                               + (uint32_t)(cur * 256 + tid) * 8u;
            float sx = 0.0f, sy = 0.0f;
            #pragma unroll
            for (int rk = 0; rk < NH; rk++) {
                float2 v = ld_dsmem2(rkb[rk] + off);
                sx += v.x;
                sy += v.y;
            }
            pf2[tid] = pack2(sx, sy);
        }
        __syncthreads();

        // ---------- phase B: uh[b][jB] += p[b][r] * U2t[jB][r], r in rh slice ----------
        {
            u64 a0 = 0, a1 = 0, a2 = 0, a3 = 0;
            const int rbase = rh * 32;
            #pragma unroll
            for (int q = 0; q < 32; q += 4) {
                float4 u4 = *(const float4*)(u2row + q);
                u64 up0 = dup2(u4.x), up1 = dup2(u4.y);
                u64 up2 = dup2(u4.z), up3 = dup2(u4.w);
                #pragma unroll
                for (int bp = 0; bp < 4; bp++) {
                    const u64* pp = pf2 + bp * 64 + rbase + q;
                    ulonglong2 pa = *(const ulonglong2*)(pp);
                    ulonglong2 pb = *(const ulonglong2*)(pp + 2);
                    u64& acc = (bp == 0) ? a0 : (bp == 1) ? a1 : (bp == 2) ? a2 : a3;
                    acc = fma2(pa.x, up0, acc);
                    acc = fma2(pa.y, up1, acc);
                    acc = fma2(pb.x, up2, acc);
                    acc = fma2(pb.y, up3, acc);
                }
            }
            red[(rh * 4 + 0) * HT + jB] = a0;
            red[(rh * 4 + 1) * HT + jB] = a1;
            red[(rh * 4 + 2) * HT + jB] = a2;
            red[(rh * 4 + 3) * HT + jB] = a3;
        }
        __syncthreads();

        // ---------- reduce rh halves + epilogue (thread owns 4 b at column jE) ----------
        {
            float wx[4] = {wxr0, wxr1, wxr2, wxr3};
            #pragma unroll
            for (int pi = 0; pi < 2; pi++) {
                int bp = bh * 2 + pi;
                u64 s = add2(red[(0 * 4 + bp) * HT + jE],
                             red[(1 * 4 + bp) * HT + jE]);
                float uh0, uh1;
                unpack2(s, uh0, uh1);
                float ho0, ho1;
                unpack2(h2[bp * HT + jE], ho0, ho1);

                float pre0 = uh0 + wx[pi * 2 + 0];
                float pre1 = uh1 + wx[pi * 2 + 1];

                float z0 = sigmoidf_(pre0 + bgv);
                float z1 = sigmoidf_(pre1 + bgv);

                float y0 = pre0 + buv, y1 = pre1 + buv;
                float e0 = __expf(-2.0f * fabsf(y0));
                float e1 = __expf(-2.0f * fabsf(y1));
                float c0 = copysignf(__fdividef(1.0f - e0, 1.0f + e0), y0);
                float c1 = copysignf(__fdividef(1.0f - e1, 1.0f + e1), y1);

                float hn0 = fmaf(fmaf(zs, 1.0f - z0, ns), c0, z0 * ho0);
                float hn1 = fmaf(fmaf(zs, 1.0f - z1, ns), c1, z1 * ho1);

                h2[bp * HT + jE] = pack2(hn0, hn1);
                size_t ob = ((size_t)t * Bb + b0 + 2 * bp) * Hh + hgb + jE;
                out[ob]      = hn0;
                out[ob + Hh] = hn1;
            }
        }
        __syncthreads();   // h2 update visible before next phase A
    }
}

// ======================================================================
// Launch
// ======================================================================
extern "C" void kernel_launch(void* const* d_in, const int* in_sizes, int n_in,
                              void* d_out, int out_size)
{
    const float* x    = (const float*)d_in[0];
    const float* h0   = (const float*)d_in[1];
    const float* W1   = (const float*)d_in[2];
    const float* W2   = (const float*)d_in[3];
    const float* U1   = (const float*)d_in[4];
    const float* U2   = (const float*)d_in[5];
    const float* bg   = (const float*)d_in[6];
    const float* bu   = (const float*)d_in[7];
    const float* zeta = (const float*)d_in[8];
    const float* nu   = (const float*)d_in[9];
    float* out = (float*)d_out;

    // 1) xw1 = x @ W1^T
    cudaFuncSetAttribute(xw1_kernel, cudaFuncAttributeMaxDynamicSharedMemorySize,
                         XW1_SMEM);
    xw1_kernel<<<(Tt * Bb) / 128, 256, XW1_SMEM>>>(x, W1);

    // 2) wx2 = xw1 @ W2^T
    const int wx2_smem = 2 * 64 * PM * sizeof(float);
    cudaFuncSetAttribute(wx2_kernel, cudaFuncAttributeMaxDynamicSharedMemorySize,
                         wx2_smem);
    dim3 g2((Tt * Bb) / 128, Hh / 128);
    wx2_kernel<<<g2, 256, wx2_smem>>>(W2);

    // 3) persistent cluster scan: 32 clusters x 8 CTAs = 256 CTAs, occ 2
    cudaFuncSetAttribute(scan_kernel, cudaFuncAttributeMaxDynamicSharedMemorySize,
                         SMEM_BYTES);
    scan_kernel<<<(Bb / BT) * NH, 256, SMEM_BYTES>>>(h0, U1, U2, bg, bu,
                                                     zeta, nu, out);
}